// round 1
// baseline (speedup 1.0000x reference)
#include <cuda_runtime.h>
#include <math.h>

// Problem constants: generated [2, 3, 96, 96]
#define B      2
#define NPIX   9216            // 96*96
#define K      8               // NUM_CLUSTERS
#define NCHUNK 4               // candidate chunks
#define CHUNK  (NPIX / NCHUNK) // 2304 candidates per chunk
#define QPB    512             // queries per CTA (256 threads x 2 queries)
#define NQG    (NPIX / QPB)    // 18 query groups per batch
#define NTHR   256

// Device scratch (allocation-free rule: __device__ globals)
__device__ float4 g_cand[B * NPIX];                       // (-2x,-2y,-2z,|c|^2)
__device__ float  g_part[B * NPIX * NCHUNK * K];          // partial top-8 (d^2, shifted back by +|q|^2)
__device__ float  g_qsum[B * NPIX];                       // per-query sum of 8 sqrt distances

// ---------------------------------------------------------------------------
// Kernel 1: pack candidates as float4(-2x,-2y,-2z, x^2+y^2+z^2)
// ---------------------------------------------------------------------------
__global__ void prep_kernel(const float* __restrict__ in) {
    int idx = blockIdx.x * blockDim.x + threadIdx.x;   // [0, B*NPIX)
    if (idx >= B * NPIX) return;
    int b = idx / NPIX;
    int i = idx - b * NPIX;
    const float* base = in + (size_t)b * 3 * NPIX;
    float x = base[i];
    float y = base[NPIX + i];
    float z = base[2 * NPIX + i];
    g_cand[idx] = make_float4(-2.0f * x, -2.0f * y, -2.0f * z,
                              x * x + y * y + z * z);
}

// ---------------------------------------------------------------------------
// Kernel 2: fused distance + register top-8 over a candidate chunk.
// Score s = |c|^2 - 2 q.c  (rank-equal to d^2; +|q|^2 added at writeout).
// ---------------------------------------------------------------------------
__global__ void __launch_bounds__(NTHR)
topk_kernel(const float* __restrict__ in) {
    __shared__ float4 sh[CHUNK];   // 2304 * 16B = 36864 B

    int bid = blockIdx.x;              // [0, B*NQG*NCHUNK) = [0,144)
    int c   = bid & (NCHUNK - 1);
    int qg  = (bid >> 2) % NQG;
    int b   = bid / (NQG * NCHUNK);

    // cooperative load of this chunk's candidates into shared
    const float4* cand = g_cand + b * NPIX + c * CHUNK;
    #pragma unroll
    for (int i = threadIdx.x; i < CHUNK; i += NTHR) sh[i] = cand[i];

    // two queries per thread
    int q0 = qg * QPB + threadIdx.x;
    int q1 = q0 + NTHR;
    const float* base = in + (size_t)b * 3 * NPIX;
    float ax = base[q0], ay = base[NPIX + q0], az = base[2 * NPIX + q0];
    float bx = base[q1], by = base[NPIX + q1], bz = base[2 * NPIX + q1];

    float t0[K], t1[K];
    #pragma unroll
    for (int k = 0; k < K; k++) { t0[k] = 3.0e30f; t1[k] = 3.0e30f; }

    __syncthreads();

    #pragma unroll 4
    for (int j = 0; j < CHUNK; j++) {
        float4 cv = sh[j];
        float d0 = fmaf(ax, cv.x, fmaf(ay, cv.y, fmaf(az, cv.z, cv.w)));
        float d1 = fmaf(bx, cv.x, fmaf(by, cv.y, fmaf(bz, cv.z, cv.w)));
        if (d0 < t0[K - 1]) {           // cold path: single bubble pass re-sorts
            t0[K - 1] = d0;
            #pragma unroll
            for (int k = K - 1; k > 0; --k) {
                float lo = fminf(t0[k - 1], t0[k]);
                float hi = fmaxf(t0[k - 1], t0[k]);
                t0[k - 1] = lo; t0[k] = hi;
            }
        }
        if (d1 < t1[K - 1]) {
            t1[K - 1] = d1;
            #pragma unroll
            for (int k = K - 1; k > 0; --k) {
                float lo = fminf(t1[k - 1], t1[k]);
                float hi = fmaxf(t1[k - 1], t1[k]);
                t1[k - 1] = lo; t1[k] = hi;
            }
        }
    }

    float q2a = fmaf(ax, ax, fmaf(ay, ay, az * az));
    float q2b = fmaf(bx, bx, fmaf(by, by, bz * bz));

    float* o0 = g_part + ((size_t)(b * NPIX + q0) * NCHUNK + c) * K;
    float* o1 = g_part + ((size_t)(b * NPIX + q1) * NCHUNK + c) * K;
    #pragma unroll
    for (int k = 0; k < K; k++) o0[k] = t0[k] + q2a;
    #pragma unroll
    for (int k = 0; k < K; k++) o1[k] = t1[k] + q2b;
}

// ---------------------------------------------------------------------------
// Kernel 3: merge the NCHUNK partial top-8 lists per query -> sum of 8 sqrt d.
// Smallest element is the self-distance (exact 0 in the reference): drop it.
// ---------------------------------------------------------------------------
__global__ void __launch_bounds__(NTHR)
merge_kernel() {
    int q = blockIdx.x * blockDim.x + threadIdx.x;   // [0, B*NPIX)
    if (q >= B * NPIX) return;
    const float* p = g_part + (size_t)q * (NCHUNK * K);

    float t[K];
    #pragma unroll
    for (int k = 0; k < K; k++) t[k] = 3.0e30f;

    #pragma unroll
    for (int j = 0; j < NCHUNK * K; j++) {
        float v = p[j];
        if (v < t[K - 1]) {
            t[K - 1] = v;
            #pragma unroll
            for (int k = K - 1; k > 0; --k) {
                float lo = fminf(t[k - 1], t[k]);
                float hi = fmaxf(t[k - 1], t[k]);
                t[k - 1] = lo; t[k] = hi;
            }
        }
    }

    // t[0] is the self-distance (reference value: exactly 0) -> contribute 0.
    float s = 0.0f;
    #pragma unroll
    for (int k = 1; k < K; k++) s += sqrtf(fmaxf(t[k], 0.0f));
    g_qsum[q] = s;
}

// ---------------------------------------------------------------------------
// Kernel 4: deterministic final reduction -> scalar  out = -mean
// ---------------------------------------------------------------------------
__global__ void __launch_bounds__(NTHR)
reduce_kernel(float* __restrict__ out) {
    __shared__ float red[NTHR];
    float s = 0.0f;
    for (int i = threadIdx.x; i < B * NPIX; i += NTHR) s += g_qsum[i];
    red[threadIdx.x] = s;
    __syncthreads();
    #pragma unroll
    for (int w = NTHR / 2; w > 0; w >>= 1) {
        if (threadIdx.x < w) red[threadIdx.x] += red[threadIdx.x + w];
        __syncthreads();
    }
    if (threadIdx.x == 0) {
        out[0] = -red[0] / (float)(B * NPIX * K);
    }
}

extern "C" void kernel_launch(void* const* d_in, const int* in_sizes, int n_in,
                              void* d_out, int out_size) {
    const float* in = (const float*)d_in[0];
    float* out = (float*)d_out;

    prep_kernel<<<(B * NPIX + NTHR - 1) / NTHR, NTHR>>>(in);
    topk_kernel<<<B * NQG * NCHUNK, NTHR>>>(in);
    merge_kernel<<<(B * NPIX + NTHR - 1) / NTHR, NTHR>>>();
    reduce_kernel<<<1, NTHR>>>(out);
}

// round 2
// speedup vs baseline: 1.1855x; 1.1855x over previous
#include <cuda_runtime.h>
#include <math.h>

// Problem constants: generated [2, 3, 96, 96]
#define B      2
#define NPIX   9216            // 96*96
#define K      8               // NUM_CLUSTERS
#define NCHUNK 8               // candidate chunks
#define CHUNK  (NPIX / NCHUNK) // 1152 candidates per chunk
#define QPB    512             // queries per CTA (256 threads x 2 queries)
#define NQG    (NPIX / QPB)    // 18 query groups per batch
#define NTHR   256
#define NMERGE ((B * NPIX) / NTHR)   // 72 merge blocks

typedef unsigned long long u64;

// Device scratch (allocation-free rule: __device__ globals)
// Candidate record: 32B = {-2x,-2x,-2y,-2y,-2z,-2z,|c|2,|c|2} as 2x ulonglong2
__device__ ulonglong2 g_cand2[B * NPIX * 2];
__device__ float      g_part[B * NPIX * NCHUNK * K];
__device__ float      g_bsum[NMERGE];

// ---- f32x2 packed helpers (Blackwell PTX) ---------------------------------
__device__ __forceinline__ u64 fma2(u64 a, u64 b, u64 c) {
    u64 d;
    asm("fma.rn.f32x2 %0, %1, %2, %3;" : "=l"(d) : "l"(a), "l"(b), "l"(c));
    return d;
}
__device__ __forceinline__ u64 pack2(float lo, float hi) {
    u64 d;
    asm("mov.b64 %0, {%1, %2};" : "=l"(d) : "f"(lo), "f"(hi));
    return d;
}
__device__ __forceinline__ float2 unpack2(u64 v) {
    float2 r;
    asm("mov.b64 {%0, %1}, %2;" : "=f"(r.x), "=f"(r.y) : "l"(v));
    return r;
}

// ---------------------------------------------------------------------------
// Kernel 1: pack candidates, components pre-duplicated for f32x2 math
// ---------------------------------------------------------------------------
__global__ void prep_kernel(const float* __restrict__ in) {
    int idx = blockIdx.x * blockDim.x + threadIdx.x;   // [0, B*NPIX)
    if (idx >= B * NPIX) return;
    int b = idx / NPIX;
    int i = idx - b * NPIX;
    const float* base = in + (size_t)b * 3 * NPIX;
    float x = base[i];
    float y = base[NPIX + i];
    float z = base[2 * NPIX + i];
    float s = x * x + y * y + z * z;
    float mx = -2.0f * x, my = -2.0f * y, mz = -2.0f * z;
    g_cand2[2 * idx]     = make_ulonglong2(pack2(mx, mx), pack2(my, my));
    g_cand2[2 * idx + 1] = make_ulonglong2(pack2(mz, mz), pack2(s, s));
}

// ---------------------------------------------------------------------------
// Kernel 2: fused packed distance + register top-8 over a candidate chunk.
// Score s = |c|^2 - 2 q.c  (rank-equal to d^2; +|q|^2 added at writeout).
// ---------------------------------------------------------------------------
__global__ void __launch_bounds__(NTHR)
topk_kernel(const float* __restrict__ in) {
    __shared__ ulonglong2 sh[CHUNK * 2];   // 1152 * 32B = 36864 B

    int bid = blockIdx.x;              // [0, B*NQG*NCHUNK) = [0,288)
    int c   = bid & (NCHUNK - 1);
    int qg  = (bid >> 3) % NQG;
    int b   = bid / (NQG * NCHUNK);

    // cooperative load of this chunk's candidates into shared
    const ulonglong2* cand = g_cand2 + (size_t)(b * NPIX + c * CHUNK) * 2;
    for (int i = threadIdx.x; i < CHUNK * 2; i += NTHR) sh[i] = cand[i];

    // two queries per thread, packed as {q0,q1}
    int q0 = qg * QPB + threadIdx.x;
    int q1 = q0 + NTHR;
    const float* base = in + (size_t)b * 3 * NPIX;
    float ax = base[q0], ay = base[NPIX + q0], az = base[2 * NPIX + q0];
    float bx = base[q1], by = base[NPIX + q1], bz = base[2 * NPIX + q1];
    u64 QX = pack2(ax, bx), QY = pack2(ay, by), QZ = pack2(az, bz);

    float t0[K], t1[K];
    #pragma unroll
    for (int k = 0; k < K; k++) { t0[k] = 3.0e30f; t1[k] = 3.0e30f; }

    __syncthreads();

    #pragma unroll 4
    for (int j = 0; j < CHUNK; j++) {
        ulonglong2 p0 = sh[2 * j];         // {cx,cx},{cy,cy}
        ulonglong2 p1 = sh[2 * j + 1];     // {cz,cz},{c2,c2}
        u64 t = fma2(QZ, p1.x, p1.y);
        t = fma2(QY, p0.y, t);
        t = fma2(QX, p0.x, t);
        float2 d = unpack2(t);
        if (d.x < t0[K - 1]) {             // cold path: single bubble pass
            t0[K - 1] = d.x;
            #pragma unroll
            for (int k = K - 1; k > 0; --k) {
                float lo = fminf(t0[k - 1], t0[k]);
                float hi = fmaxf(t0[k - 1], t0[k]);
                t0[k - 1] = lo; t0[k] = hi;
            }
        }
        if (d.y < t1[K - 1]) {
            t1[K - 1] = d.y;
            #pragma unroll
            for (int k = K - 1; k > 0; --k) {
                float lo = fminf(t1[k - 1], t1[k]);
                float hi = fmaxf(t1[k - 1], t1[k]);
                t1[k - 1] = lo; t1[k] = hi;
            }
        }
    }

    float q2a = fmaf(ax, ax, fmaf(ay, ay, az * az));
    float q2b = fmaf(bx, bx, fmaf(by, by, bz * bz));

    float* o0 = g_part + ((size_t)(b * NPIX + q0) * NCHUNK + c) * K;
    float* o1 = g_part + ((size_t)(b * NPIX + q1) * NCHUNK + c) * K;
    #pragma unroll
    for (int k = 0; k < K; k++) o0[k] = t0[k] + q2a;
    #pragma unroll
    for (int k = 0; k < K; k++) o1[k] = t1[k] + q2b;
}

// ---------------------------------------------------------------------------
// Kernel 3: merge NCHUNK partial top-8 lists per query -> sum of sqrt d,
// then block-reduce to one partial sum per block.
// Smallest element is the self-distance (exact 0 in reference): drop it.
// ---------------------------------------------------------------------------
__global__ void __launch_bounds__(NTHR)
merge_kernel() {
    __shared__ float red[NTHR];
    int q = blockIdx.x * blockDim.x + threadIdx.x;   // [0, B*NPIX)
    const float* p = g_part + (size_t)q * (NCHUNK * K);

    float t[K];
    #pragma unroll
    for (int k = 0; k < K; k++) t[k] = 3.0e30f;

    #pragma unroll
    for (int j = 0; j < NCHUNK * K; j++) {
        float v = p[j];
        if (v < t[K - 1]) {
            t[K - 1] = v;
            #pragma unroll
            for (int k = K - 1; k > 0; --k) {
                float lo = fminf(t[k - 1], t[k]);
                float hi = fmaxf(t[k - 1], t[k]);
                t[k - 1] = lo; t[k] = hi;
            }
        }
    }

    // t[0] is the self-distance (reference value: exactly 0) -> contribute 0.
    float s = 0.0f;
    #pragma unroll
    for (int k = 1; k < K; k++) s += sqrtf(fmaxf(t[k], 0.0f));

    red[threadIdx.x] = s;
    __syncthreads();
    #pragma unroll
    for (int w = NTHR / 2; w > 0; w >>= 1) {
        if (threadIdx.x < w) red[threadIdx.x] += red[threadIdx.x + w];
        __syncthreads();
    }
    if (threadIdx.x == 0) g_bsum[blockIdx.x] = red[0];
}

// ---------------------------------------------------------------------------
// Kernel 4: deterministic final reduction over NMERGE block sums
// ---------------------------------------------------------------------------
__global__ void __launch_bounds__(128)
reduce_kernel(float* __restrict__ out) {
    __shared__ float red[128];
    float s = (threadIdx.x < NMERGE) ? g_bsum[threadIdx.x] : 0.0f;
    red[threadIdx.x] = s;
    __syncthreads();
    #pragma unroll
    for (int w = 64; w > 0; w >>= 1) {
        if (threadIdx.x < w) red[threadIdx.x] += red[threadIdx.x + w];
        __syncthreads();
    }
    if (threadIdx.x == 0) out[0] = -red[0] / (float)(B * NPIX * K);
}

extern "C" void kernel_launch(void* const* d_in, const int* in_sizes, int n_in,
                              void* d_out, int out_size) {
    const float* in = (const float*)d_in[0];
    float* out = (float*)d_out;

    prep_kernel<<<(B * NPIX + NTHR - 1) / NTHR, NTHR>>>(in);
    topk_kernel<<<B * NQG * NCHUNK, NTHR>>>(in);
    merge_kernel<<<NMERGE, NTHR>>>();
    reduce_kernel<<<1, 128>>>(out);
}